// round 1
// baseline (speedup 1.0000x reference)
#include <cuda_runtime.h>
#include <cuda_bf16.h>
#include <math_constants.h>

#define FULL 0xffffffffu

static constexpr int B = 8;
static constexpr int N = 4096;
static constexpr int C = 128;
static constexpr int KNN = 16;

// 16MB scratch for zbn[b][n][c] (n-major so neighbor gathers are contiguous)
__device__ float g_zbn[B * N * C];

// ---------------------------------------------------------------------------
// Kernel 1: zbn[b][n][c] = relu(scale_c * (sum_k W[c][k] * x[b][k][n]) + bias_c)
// Block: 256 threads, tile 64 n x 128 c. Grid: (N/64, B).
// ---------------------------------------------------------------------------
__global__ __launch_bounds__(256) void gemm_bn_relu_kernel(
    const float* __restrict__ x,      // [B][C][N]
    const float* __restrict__ W,      // [C_out][C_in]
    const float* __restrict__ gamma,
    const float* __restrict__ beta,
    const float* __restrict__ rmean,
    const float* __restrict__ rvar)
{
    __shared__ float xs[32][64];    // [k][n]
    __shared__ float ws[32][128];   // [k][c], XOR-swizzled in 4-float units

    const int b  = blockIdx.y;
    const int n0 = blockIdx.x * 64;
    const int tid = threadIdx.x;
    const int tc = tid & 31;   // c-group: c = tc*4 + j   (varies across warp lanes)
    const int tn = tid >> 5;   // n-group: n = n0 + tn*8 + i

    float acc[4][8];
#pragma unroll
    for (int j = 0; j < 4; ++j)
#pragma unroll
        for (int i = 0; i < 8; ++i) acc[j][i] = 0.0f;

    const float* xb = x + (size_t)b * C * N;

    for (int k0 = 0; k0 < C; k0 += 32) {
        // load x tile: 32k x 64n, coalesced
#pragma unroll
        for (int i = tid; i < 32 * 64; i += 256) {
            int kk = i >> 6, nn = i & 63;
            xs[kk][nn] = xb[(size_t)(k0 + kk) * N + n0 + nn];
        }
        // load W tile: ws[kk][c ^ ((kk&7)<<2)] = W[c][k0+kk]  (coalesced global read)
#pragma unroll
        for (int i = tid; i < 32 * 128; i += 256) {
            int c = i >> 5, kk = i & 31;
            ws[kk][c ^ ((kk & 7) << 2)] = W[c * C + k0 + kk];
        }
        __syncthreads();

#pragma unroll
        for (int kk = 0; kk < 32; ++kk) {
            float4 wv  = *(const float4*)&ws[kk][((tc ^ (kk & 7)) << 2)];
            float4 xv0 = *(const float4*)&xs[kk][tn * 8];
            float4 xv1 = *(const float4*)&xs[kk][tn * 8 + 4];
            float wj[4] = {wv.x, wv.y, wv.z, wv.w};
            float xi[8] = {xv0.x, xv0.y, xv0.z, xv0.w, xv1.x, xv1.y, xv1.z, xv1.w};
#pragma unroll
            for (int j = 0; j < 4; ++j)
#pragma unroll
                for (int i = 0; i < 8; ++i)
                    acc[j][i] = fmaf(wj[j], xi[i], acc[j][i]);
        }
        __syncthreads();
    }

    // epilogue: BN + ReLU, store [b][n][c] with c contiguous (coalesced float4)
    const int c0 = tc * 4;
    float sc[4], bi[4];
#pragma unroll
    for (int j = 0; j < 4; ++j) {
        sc[j] = gamma[c0 + j] * rsqrtf(rvar[c0 + j] + 1e-5f);
        bi[j] = beta[c0 + j] - rmean[c0 + j] * sc[j];
    }
#pragma unroll
    for (int i = 0; i < 8; ++i) {
        int n = n0 + tn * 8 + i;
        float4 o;
        o.x = fmaxf(fmaf(acc[0][i], sc[0], bi[0]), 0.0f);
        o.y = fmaxf(fmaf(acc[1][i], sc[1], bi[1]), 0.0f);
        o.z = fmaxf(fmaf(acc[2][i], sc[2], bi[2]), 0.0f);
        o.w = fmaxf(fmaf(acc[3][i], sc[3], bi[3]), 0.0f);
        *(float4*)&g_zbn[((size_t)b * N + n) * C + c0] = o;
    }
}

// ---------------------------------------------------------------------------
// Kernel 2: per-query KNN (warp-distributed sorted top-16) + gather-max.
// Block: 256 threads (8 warps), each warp does 4 queries -> 32 queries/block.
// Grid: (N/32, B). Dynamic smem: xyz4[4096] (x,y,z,|p|^2) = 64KB.
// ---------------------------------------------------------------------------
__global__ __launch_bounds__(256) void knn_gather_kernel(
    const float* __restrict__ xyz,   // [B][N][3]
    float* __restrict__ out)         // [B][C][N]
{
    extern __shared__ float4 sxyz[];        // [4096]
    __shared__ float sout[128][33];         // transpose buffer (padded)

    const int b   = blockIdx.y;
    const int n0  = blockIdx.x * 32;
    const int tid = threadIdx.x;
    const int w   = tid >> 5;
    const int lane = tid & 31;

    // stage xyz for this batch + precompute squared norms
    const float* xb = xyz + (size_t)b * N * 3;
    for (int j = tid; j < N; j += 256) {
        float px = xb[3 * j], py = xb[3 * j + 1], pz = xb[3 * j + 2];
        sxyz[j] = make_float4(px, py, pz, px * px + py * py + pz * pz);
    }
    __syncthreads();

    const float* zb = g_zbn + (size_t)b * N * C;

    for (int s = 0; s < 4; ++s) {
        const int ql = w * 4 + s;
        const int n  = n0 + ql;
        const float4 q = sxyz[n];
        const float qs = q.w;

        // lanes 0..31 hold a sorted (ascending) list; we care about lanes 0..15
        float topv = CUDART_INF_F;
        int   topi = 0;
        float thresh = CUDART_INF_F;

        for (int j0 = 0; j0 < N; j0 += 32) {
            float4 p = sxyz[j0 + lane];
            float dot = q.x * p.x;
            dot = fmaf(q.y, p.y, dot);
            dot = fmaf(q.z, p.z, dot);
            float d = fmaf(-2.0f, dot, qs + p.w);   // = s_i + s_j - 2*dot

            unsigned mask = __ballot_sync(FULL, d < thresh);
            while (mask) {
                int src = __ffs(mask) - 1;
                mask &= mask - 1;
                float v  = __shfl_sync(FULL, d, src);
                int   vi = j0 + src;
                float upv = __shfl_up_sync(FULL, topv, 1);
                int   upi = __shfl_up_sync(FULL, topi, 1);
                bool sh = (topv > v);
                unsigned bal = __ballot_sync(FULL, sh);
                if (sh) {
                    int first = __ffs(bal) - 1;
                    bool here = (lane == first);
                    topv = here ? v  : upv;
                    topi = here ? vi : upi;
                }
                thresh = __shfl_sync(FULL, topv, 15);
            }
        }

        // gather-max over the 16 nearest (zbn rows are 512B contiguous, L2-hot)
        float m0 = 0.0f, m1 = 0.0f, m2 = 0.0f, m3 = 0.0f;  // post-ReLU values >= 0
#pragma unroll
        for (int t = 0; t < KNN; t += 2) {
            int j1 = __shfl_sync(FULL, topi, t);
            int j2 = __shfl_sync(FULL, topi, t + 1);
            const float* c1 = zb + ((size_t)j1 << 7);
            const float* c2 = zb + ((size_t)j2 << 7);
            float a0 = c1[lane],      a1 = c1[lane + 32], a2 = c1[lane + 64], a3 = c1[lane + 96];
            float b0 = c2[lane],      b1 = c2[lane + 32], b2 = c2[lane + 64], b3 = c2[lane + 96];
            m0 = fmaxf(m0, fmaxf(a0, b0));
            m1 = fmaxf(m1, fmaxf(a1, b1));
            m2 = fmaxf(m2, fmaxf(a2, b2));
            m3 = fmaxf(m3, fmaxf(a3, b3));
        }

        sout[lane][ql]      = m0;
        sout[lane + 32][ql] = m1;
        sout[lane + 64][ql] = m2;
        sout[lane + 96][ql] = m3;
    }
    __syncthreads();

    // coalesced write-out: out[b][c][n0 .. n0+31]
    float* ob = out + (size_t)b * C * N + n0;
    for (int i = tid; i < 128 * 32; i += 256) {
        int c = i >> 5, nn = i & 31;
        ob[(size_t)c * N + nn] = sout[c][nn];
    }
}

// ---------------------------------------------------------------------------
extern "C" void kernel_launch(void* const* d_in, const int* in_sizes, int n_in,
                              void* d_out, int out_size)
{
    const float* xyz   = (const float*)d_in[0];
    const float* x     = (const float*)d_in[1];
    const float* W     = (const float*)d_in[2];
    const float* gamma = (const float*)d_in[3];
    const float* beta  = (const float*)d_in[4];
    const float* rmean = (const float*)d_in[5];
    const float* rvar  = (const float*)d_in[6];
    float* out = (float*)d_out;

    cudaFuncSetAttribute(knn_gather_kernel,
                         cudaFuncAttributeMaxDynamicSharedMemorySize,
                         N * (int)sizeof(float4));

    gemm_bn_relu_kernel<<<dim3(N / 64, B), 256>>>(x, W, gamma, beta, rmean, rvar);
    knn_gather_kernel<<<dim3(N / 32, B), 256, N * sizeof(float4)>>>(xyz, out);
}